// round 12
// baseline (speedup 1.0000x reference)
#include <cuda_runtime.h>
#include <cuda_fp16.h>
#include <cstdint>

// Problem constants
#define NUM_FIELDS 16
#define EMBED      256
#define BATCH      2048
#define NUM_PAIRS  120

// Tiling: CTA 128x256 (full N), 8 warps (2x4), warp tile 64x64, BK=64, fp16 m16n8k16
#define BM 128
#define BN 256
#define BK 64
#define THREADS 256

#define STRIDE 72                     // halfs; fragment banks 4g+t4 distinct (proven R9-R11)
#define TILE_A_HALFS (BM * STRIDE)    // 9216
#define TILE_B_HALFS (BN * STRIDE)    // 18432
#define SMEM_BYTES ((2 * TILE_A_HALFS + 2 * TILE_B_HALFS) * 2)   // 110592 B

// fp16 copies (allocation-free rule: __device__ globals)
__device__ __half g_Wt[(size_t)NUM_PAIRS * EMBED * EMBED];   // W^T: [p][f][e]
__device__ __half g_embh[(size_t)BATCH * NUM_FIELDS * EMBED];

__device__ __forceinline__ uint32_t smem_u32(const void* p) {
    return (uint32_t)__cvta_generic_to_shared(p);
}
__device__ __forceinline__ void cp_async16(uint32_t dst, const void* src) {
    asm volatile("cp.async.cg.shared.global [%0], [%1], 16;\n" :: "r"(dst), "l"(src));
}
__device__ __forceinline__ void cp_commit() {
    asm volatile("cp.async.commit_group;\n" ::: "memory");
}
__device__ __forceinline__ void mma_f16(float c[4], const uint32_t a[4], const uint32_t b[2]) {
    asm volatile(
        "mma.sync.aligned.m16n8k16.row.col.f32.f16.f16.f32 "
        "{%0,%1,%2,%3}, {%4,%5,%6,%7}, {%8,%9}, {%0,%1,%2,%3};\n"
        : "+f"(c[0]), "+f"(c[1]), "+f"(c[2]), "+f"(c[3])
        : "r"(a[0]), "r"(a[1]), "r"(a[2]), "r"(a[3]), "r"(b[0]), "r"(b[1]));
}

// ---------------- fused prep kernel ----------------
#define WBLOCKS 7680
#define EBLOCKS 2048

__global__ void prep_all(const float* __restrict__ w, const float4* __restrict__ e) {
    __shared__ float t[32][33];
    const int b = blockIdx.x;
    const int tid = threadIdx.x;

    if (b < WBLOCKS) {
        const int p   = b >> 6;
        const int til = b & 63;
        const int f0  = (til & 7) * 32;
        const int e0  = (til >> 3) * 32;
        const int tx = tid & 31, ty = tid >> 5;   // 32 x 8
        const float* W = w + (size_t)p * EMBED * EMBED;
        #pragma unroll
        for (int r = 0; r < 4; ++r)
            t[ty + 8 * r][tx] = W[(size_t)(e0 + ty + 8 * r) * EMBED + f0 + tx];
        __syncthreads();
        __half* Wt = g_Wt + (size_t)p * EMBED * EMBED;
        #pragma unroll
        for (int r = 0; r < 4; ++r)
            Wt[(size_t)(f0 + ty + 8 * r) * EMBED + e0 + tx] =
                __float2half_rn(t[tx][ty + 8 * r]);
    } else {
        const size_t base = (size_t)(b - WBLOCKS) * 1024 + tid;
        #pragma unroll
        for (int it = 0; it < 4; ++it) {
            const size_t idx = base + (size_t)it * 256;
            float4 v = e[idx];
            __half2 lo = __floats2half2_rn(v.x, v.y);
            __half2 hi = __floats2half2_rn(v.z, v.w);
            reinterpret_cast<__half2*>(g_embh)[idx * 2 + 0] = lo;
            reinterpret_cast<__half2*>(g_embh)[idx * 2 + 1] = hi;
        }
    }
}

// ---------------- main kernel ----------------
__global__ void __launch_bounds__(THREADS, 1)
bilinear_kernel(const float* __restrict__ emb,
                const float* __restrict__ bias,
                float* __restrict__ out)
{
    extern __shared__ __half sm[];
    __half* Asm = sm;                        // 2 stages x TILE_A_HALFS
    __half* Bsm = sm + 2 * TILE_A_HALFS;     // 2 stages x TILE_B_HALFS

    const int p   = blockIdx.y;
    const int bm0 = blockIdx.x * BM;

    // pair p -> (i, j) of triu_indices(16, k=1)
    int i = 0, rem = p;
    while (rem >= (NUM_FIELDS - 1) - i) { rem -= (NUM_FIELDS - 1) - i; ++i; }
    const int j = i + 1 + rem;

    const int tid  = threadIdx.x;
    const int lane = tid & 31;
    const int warp = tid >> 5;    // 0..7
    const int wm   = warp >> 2;   // 0..1  (64-row slab)
    const int wn   = warp & 3;    // 0..3  (64-col slab)
    const int g    = lane >> 2;   // 0..7
    const int t4   = lane & 3;    // 0..3

    const __half* Aglob = g_embh + (size_t)bm0 * (NUM_FIELDS * EMBED) + (size_t)i * EMBED;
    const __half* Bglob = g_Wt + (size_t)p * (EMBED * EMBED);

    float acc[4][8][4];
    #pragma unroll
    for (int mi = 0; mi < 4; ++mi)
        #pragma unroll
        for (int ni = 0; ni < 8; ++ni)
            #pragma unroll
            for (int r = 0; r < 4; ++r)
                acc[mi][ni][r] = 0.0f;

    // ---- async tile loaders -----------------------------------------------
    // A chunk: 128 rows x 64 halfs = 1024 x 16B -> 4 per thread
    // B chunk: 256 rows x 64 halfs = 2048 x 16B -> 8 per thread
    auto load_tiles = [&](int buf, int k0) {
        __half* Ad = Asm + buf * TILE_A_HALFS;
        __half* Bd = Bsm + buf * TILE_B_HALFS;
        #pragma unroll
        for (int it = 0; it < 4; ++it) {
            int idx = tid + it * THREADS;
            int m   = idx >> 3;          // 0..127
            int q   = idx & 7;           // 8-half chunk
            cp_async16(smem_u32(Ad + m * STRIDE + q * 8),
                       Aglob + (size_t)m * (NUM_FIELDS * EMBED) + k0 + q * 8);
        }
        #pragma unroll
        for (int it = 0; it < 8; ++it) {
            int idx = tid + it * THREADS;
            int n   = idx >> 3;          // 0..255
            int q   = idx & 7;
            cp_async16(smem_u32(Bd + n * STRIDE + q * 8),
                       Bglob + (size_t)n * EMBED + k0 + q * 8);
        }
    };

    const int NK = EMBED / BK;   // 4

    load_tiles(0, 0);
    cp_commit();

    for (int kt = 0; kt < NK; ++kt) {
        if (kt + 1 < NK) {
            load_tiles((kt + 1) & 1, (kt + 1) * BK);
            cp_commit();
            asm volatile("cp.async.wait_group 1;\n" ::: "memory");
        } else {
            asm volatile("cp.async.wait_group 0;\n" ::: "memory");
        }
        __syncthreads();

        const __half* Ab = Asm + (kt & 1) * TILE_A_HALFS;
        const __half* Bb = Bsm + (kt & 1) * TILE_B_HALFS;

        #pragma unroll
        for (int ks = 0; ks < BK / 16; ++ks) {
            const int kk = ks * 16;

            uint32_t afrag[4][4];
            #pragma unroll
            for (int mi = 0; mi < 4; ++mi) {
                const int rm = wm * 64 + mi * 16;
                afrag[mi][0] = *(const uint32_t*)(Ab + (rm + g    ) * STRIDE + kk + 2 * t4    );
                afrag[mi][1] = *(const uint32_t*)(Ab + (rm + g + 8) * STRIDE + kk + 2 * t4    );
                afrag[mi][2] = *(const uint32_t*)(Ab + (rm + g    ) * STRIDE + kk + 2 * t4 + 8);
                afrag[mi][3] = *(const uint32_t*)(Ab + (rm + g + 8) * STRIDE + kk + 2 * t4 + 8);
            }
            uint32_t bfrag[8][2];
            #pragma unroll
            for (int ni = 0; ni < 8; ++ni) {
                const int cn = wn * 64 + ni * 8 + g;
                bfrag[ni][0] = *(const uint32_t*)(Bb + cn * STRIDE + kk + 2 * t4    );
                bfrag[ni][1] = *(const uint32_t*)(Bb + cn * STRIDE + kk + 2 * t4 + 8);
            }
            #pragma unroll
            for (int mi = 0; mi < 4; ++mi)
                #pragma unroll
                for (int ni = 0; ni < 8; ++ni)
                    mma_f16(acc[mi][ni], afrag[mi], bfrag[ni]);
        }
        __syncthreads();
    }

    // ---- epilogue: out[b,p,f] = acc * emb[b,j,f] + bias[p,f] ---------------
    const float* biasP = bias + (size_t)p * EMBED;

    #pragma unroll
    for (int mi = 0; mi < 4; ++mi) {
        const int r0 = bm0 + wm * 64 + mi * 16 + g;
        #pragma unroll
        for (int ni = 0; ni < 8; ++ni) {
            const int c = wn * 64 + ni * 8 + t4 * 2;
            const float2 bb = *(const float2*)(biasP + c);
            #pragma unroll
            for (int h = 0; h < 2; ++h) {
                const int row = r0 + h * 8;
                const float2 q = *(const float2*)(emb + (size_t)row * (NUM_FIELDS * EMBED)
                                                   + (size_t)j * EMBED + c);
                float2 v;
                v.x = acc[mi][ni][h * 2 + 0] * q.x + bb.x;
                v.y = acc[mi][ni][h * 2 + 1] * q.y + bb.y;
                *(float2*)(out + (size_t)row * (NUM_PAIRS * EMBED) + (size_t)p * EMBED + c) = v;
            }
        }
    }
}

extern "C" void kernel_launch(void* const* d_in, const int* in_sizes, int n_in,
                              void* d_out, int out_size) {
    const float* emb    = (const float*)d_in[0];
    const float* weight = (const float*)d_in[1];
    const float* bias   = (const float*)d_in[2];
    float* out          = (float*)d_out;

    cudaFuncSetAttribute(bilinear_kernel,
                         cudaFuncAttributeMaxDynamicSharedMemorySize, SMEM_BYTES);

    prep_all<<<WBLOCKS + EBLOCKS, 256>>>(weight, (const float4*)emb);

    dim3 grid(BATCH / BM, NUM_PAIRS);   // (16, 120)
    bilinear_kernel<<<grid, THREADS, SMEM_BYTES>>>(emb, bias, out);
}

// round 13
// speedup vs baseline: 1.0904x; 1.0904x over previous
#include <cuda_runtime.h>
#include <cuda_fp16.h>
#include <cstdint>

// Problem constants
#define NUM_FIELDS 16
#define EMBED      256
#define BATCH      2048
#define NUM_PAIRS  120

// Tiling: CTA 128x128 with 4 warps (2x2), warp tile 64x64, BK=64, fp16 m16n8k16
// 3-stage cp.async pipeline, 2 CTAs/SM
#define BM 128
#define BN 128
#define BK 64
#define THREADS 128
#define NSTAGE 3

#define STRIDE 72                 // halfs; fragment banks conflict-free (proven R9-R11)
#define TILE_HALFS (128 * STRIDE) // per operand per stage = 9216
#define SMEM_BYTES (NSTAGE * 2 * TILE_HALFS * 2)   // 110592 B

// fp16 copies (allocation-free rule: __device__ globals)
__device__ __half g_Wt[(size_t)NUM_PAIRS * EMBED * EMBED];   // W^T: [p][f][e]
__device__ __half g_embh[(size_t)BATCH * NUM_FIELDS * EMBED];

__device__ __forceinline__ uint32_t smem_u32(const void* p) {
    return (uint32_t)__cvta_generic_to_shared(p);
}
__device__ __forceinline__ void cp_async16(uint32_t dst, const void* src) {
    asm volatile("cp.async.cg.shared.global [%0], [%1], 16;\n" :: "r"(dst), "l"(src));
}
__device__ __forceinline__ void cp_commit() {
    asm volatile("cp.async.commit_group;\n" ::: "memory");
}
__device__ __forceinline__ void mma_f16(float c[4], const uint32_t a[4], const uint32_t b[2]) {
    asm volatile(
        "mma.sync.aligned.m16n8k16.row.col.f32.f16.f16.f32 "
        "{%0,%1,%2,%3}, {%4,%5,%6,%7}, {%8,%9}, {%0,%1,%2,%3};\n"
        : "+f"(c[0]), "+f"(c[1]), "+f"(c[2]), "+f"(c[3])
        : "r"(a[0]), "r"(a[1]), "r"(a[2]), "r"(a[3]), "r"(b[0]), "r"(b[1]));
}

// ---------------- fused prep kernel ----------------
#define WBLOCKS 7680
#define EBLOCKS 2048

__global__ void prep_all(const float* __restrict__ w, const float4* __restrict__ e) {
    __shared__ float t[32][33];
    const int b = blockIdx.x;
    const int tid = threadIdx.x;

    if (b < WBLOCKS) {
        const int p   = b >> 6;
        const int til = b & 63;
        const int f0  = (til & 7) * 32;
        const int e0  = (til >> 3) * 32;
        const int tx = tid & 31, ty = tid >> 5;   // 32 x 8
        const float* W = w + (size_t)p * EMBED * EMBED;
        #pragma unroll
        for (int r = 0; r < 4; ++r)
            t[ty + 8 * r][tx] = W[(size_t)(e0 + ty + 8 * r) * EMBED + f0 + tx];
        __syncthreads();
        __half* Wt = g_Wt + (size_t)p * EMBED * EMBED;
        #pragma unroll
        for (int r = 0; r < 4; ++r)
            Wt[(size_t)(f0 + ty + 8 * r) * EMBED + e0 + tx] =
                __float2half_rn(t[tx][ty + 8 * r]);
    } else {
        const size_t base = (size_t)(b - WBLOCKS) * 1024 + tid;
        #pragma unroll
        for (int it = 0; it < 4; ++it) {
            const size_t idx = base + (size_t)it * 256;
            float4 v = e[idx];
            __half2 lo = __floats2half2_rn(v.x, v.y);
            __half2 hi = __floats2half2_rn(v.z, v.w);
            reinterpret_cast<__half2*>(g_embh)[idx * 2 + 0] = lo;
            reinterpret_cast<__half2*>(g_embh)[idx * 2 + 1] = hi;
        }
    }
}

// ---------------- main kernel ----------------
__global__ void __launch_bounds__(THREADS, 2)
bilinear_kernel(const float* __restrict__ emb,
                const float* __restrict__ bias,
                float* __restrict__ out)
{
    extern __shared__ __half sm[];
    __half* Asm = sm;                           // NSTAGE x TILE_HALFS
    __half* Bsm = sm + NSTAGE * TILE_HALFS;     // NSTAGE x TILE_HALFS

    const int p   = blockIdx.z;
    const int bm0 = blockIdx.x * BM;
    const int bn0 = blockIdx.y * BN;

    // pair p -> (i, j) of triu_indices(16, k=1)
    int i = 0, rem = p;
    while (rem >= (NUM_FIELDS - 1) - i) { rem -= (NUM_FIELDS - 1) - i; ++i; }
    const int j = i + 1 + rem;

    const int tid  = threadIdx.x;
    const int lane = tid & 31;
    const int warp = tid >> 5;    // 0..3
    const int wm   = warp >> 1;   // 0..1  (64-row slab)
    const int wn   = warp & 1;    // 0..1  (64-col slab)
    const int g    = lane >> 2;   // 0..7
    const int t4   = lane & 3;    // 0..3

    const __half* Aglob = g_embh + (size_t)bm0 * (NUM_FIELDS * EMBED) + (size_t)i * EMBED;
    const __half* Bglob = g_Wt + (size_t)p * (EMBED * EMBED) + (size_t)bn0 * EMBED;

    float acc[4][8][4];
    #pragma unroll
    for (int mi = 0; mi < 4; ++mi)
        #pragma unroll
        for (int ni = 0; ni < 8; ++ni)
            #pragma unroll
            for (int r = 0; r < 4; ++r)
                acc[mi][ni][r] = 0.0f;

    // ---- async tile loaders: 128 rows x 64 halfs = 1024 x 16B per operand --
    auto load_tiles = [&](int buf, int k0) {
        __half* Ad = Asm + buf * TILE_HALFS;
        __half* Bd = Bsm + buf * TILE_HALFS;
        #pragma unroll
        for (int it = 0; it < 8; ++it) {
            int idx = tid + it * THREADS;
            int m   = idx >> 3;          // 0..127
            int q   = idx & 7;           // 8-half chunk
            cp_async16(smem_u32(Ad + m * STRIDE + q * 8),
                       Aglob + (size_t)m * (NUM_FIELDS * EMBED) + k0 + q * 8);
        }
        #pragma unroll
        for (int it = 0; it < 8; ++it) {
            int idx = tid + it * THREADS;
            int n   = idx >> 3;
            int q   = idx & 7;
            cp_async16(smem_u32(Bd + n * STRIDE + q * 8),
                       Bglob + (size_t)n * EMBED + k0 + q * 8);
        }
        cp_commit();
    };

    const int NK = EMBED / BK;   // 4

    // prologue: stages 0 and 1 in flight
    load_tiles(0, 0);
    load_tiles(1, BK);

    for (int kt = 0; kt < NK; ++kt) {
        // wait for stage kt to be resident
        if (kt < NK - 1) asm volatile("cp.async.wait_group 1;\n" ::: "memory");
        else             asm volatile("cp.async.wait_group 0;\n" ::: "memory");
        // single barrier: data visible + all warps finished reading stage (kt+2)%NSTAGE
        __syncthreads();

        // refill the stage last read at kt-1
        if (kt + 2 < NK)
            load_tiles((kt + 2) % NSTAGE, (kt + 2) * BK);

        const __half* Ab = Asm + (kt % NSTAGE) * TILE_HALFS;
        const __half* Bb = Bsm + (kt % NSTAGE) * TILE_HALFS;

        #pragma unroll
        for (int ks = 0; ks < BK / 16; ++ks) {
            const int kk = ks * 16;

            uint32_t afrag[4][4];
            #pragma unroll
            for (int mi = 0; mi < 4; ++mi) {
                const int rm = wm * 64 + mi * 16;
                afrag[mi][0] = *(const uint32_t*)(Ab + (rm + g    ) * STRIDE + kk + 2 * t4    );
                afrag[mi][1] = *(const uint32_t*)(Ab + (rm + g + 8) * STRIDE + kk + 2 * t4    );
                afrag[mi][2] = *(const uint32_t*)(Ab + (rm + g    ) * STRIDE + kk + 2 * t4 + 8);
                afrag[mi][3] = *(const uint32_t*)(Ab + (rm + g + 8) * STRIDE + kk + 2 * t4 + 8);
            }
            uint32_t bfrag[8][2];
            #pragma unroll
            for (int ni = 0; ni < 8; ++ni) {
                const int cn = wn * 64 + ni * 8 + g;
                bfrag[ni][0] = *(const uint32_t*)(Bb + cn * STRIDE + kk + 2 * t4    );
                bfrag[ni][1] = *(const uint32_t*)(Bb + cn * STRIDE + kk + 2 * t4 + 8);
            }
            #pragma unroll
            for (int mi = 0; mi < 4; ++mi)
                #pragma unroll
                for (int ni = 0; ni < 8; ++ni)
                    mma_f16(acc[mi][ni], afrag[mi], bfrag[ni]);
        }
    }

    // ---- epilogue: out[b,p,f] = acc * emb[b,j,f] + bias[p,f] ---------------
    const float* biasP = bias + (size_t)p * EMBED;

    #pragma unroll
    for (int mi = 0; mi < 4; ++mi) {
        const int r0 = bm0 + wm * 64 + mi * 16 + g;
        #pragma unroll
        for (int ni = 0; ni < 8; ++ni) {
            const int c = bn0 + wn * 64 + ni * 8 + t4 * 2;
            const float2 bb = *(const float2*)(biasP + c);
            #pragma unroll
            for (int h = 0; h < 2; ++h) {
                const int row = r0 + h * 8;
                const float2 q = *(const float2*)(emb + (size_t)row * (NUM_FIELDS * EMBED)
                                                   + (size_t)j * EMBED + c);
                float2 v;
                v.x = acc[mi][ni][h * 2 + 0] * q.x + bb.x;
                v.y = acc[mi][ni][h * 2 + 1] * q.y + bb.y;
                *(float2*)(out + (size_t)row * (NUM_PAIRS * EMBED) + (size_t)p * EMBED + c) = v;
            }
        }
    }
}

extern "C" void kernel_launch(void* const* d_in, const int* in_sizes, int n_in,
                              void* d_out, int out_size) {
    const float* emb    = (const float*)d_in[0];
    const float* weight = (const float*)d_in[1];
    const float* bias   = (const float*)d_in[2];
    float* out          = (float*)d_out;

    cudaFuncSetAttribute(bilinear_kernel,
                         cudaFuncAttributeMaxDynamicSharedMemorySize, SMEM_BYTES);

    prep_all<<<WBLOCKS + EBLOCKS, 256>>>(weight, (const float4*)emb);

    dim3 grid(BATCH / BM, EMBED / BN, NUM_PAIRS);   // (16, 2, 120)
    bilinear_kernel<<<grid, THREADS, SMEM_BYTES>>>(emb, bias, out);
}

// round 16
// speedup vs baseline: 1.1045x; 1.0129x over previous
#include <cuda_runtime.h>
#include <cuda_fp16.h>
#include <cstdint>

// Problem constants
#define NUM_FIELDS 16
#define EMBED      256
#define BATCH      2048
#define NUM_PAIRS  120

// Tiling: CTA 128x128 with 4 warps (2x2), warp tile 64x64, BK=64, fp16 m16n8k16
#define BM 128
#define BN 128
#define BK 64
#define THREADS 128

#define STRIDE 72                 // halfs; fragment banks conflict-free (proven R9-R11)
#define TILE_HALFS (128 * STRIDE) // per operand per stage
#define SMEM_BYTES (4 * TILE_HALFS * 2)   // A0,A1,B0,B1 = 73728 B

// fp16 copies (allocation-free rule: __device__ globals)
__device__ __half g_Wt[(size_t)NUM_PAIRS * EMBED * EMBED];   // W^T: [p][f][e]
__device__ __half g_embh[(size_t)BATCH * NUM_FIELDS * EMBED];

__device__ __forceinline__ uint32_t smem_u32(const void* p) {
    return (uint32_t)__cvta_generic_to_shared(p);
}
__device__ __forceinline__ void cp_async16(uint32_t dst, const void* src) {
    asm volatile("cp.async.cg.shared.global [%0], [%1], 16;\n" :: "r"(dst), "l"(src));
}
__device__ __forceinline__ void cp_commit() {
    asm volatile("cp.async.commit_group;\n" ::: "memory");
}
__device__ __forceinline__ uint32_t h2_bits(__half2 h) {
    return *reinterpret_cast<uint32_t*>(&h);
}
__device__ __forceinline__ void mma_f16(float c[4], const uint32_t a[4], const uint32_t b[2]) {
    asm volatile(
        "mma.sync.aligned.m16n8k16.row.col.f32.f16.f16.f32 "
        "{%0,%1,%2,%3}, {%4,%5,%6,%7}, {%8,%9}, {%0,%1,%2,%3};\n"
        : "+f"(c[0]), "+f"(c[1]), "+f"(c[2]), "+f"(c[3])
        : "r"(a[0]), "r"(a[1]), "r"(a[2]), "r"(a[3]), "r"(b[0]), "r"(b[1]));
}

// ---------------- fused prep kernel (vectorized stores) ----------------
// Blocks [0, 3840):   W^T tiles of 64(e) x 32(f); half2 stores, 128B/warp
// Blocks [3840, 4864): emb fp16 convert, 2 float4 -> uint4 (16B) per thread
#define WBLOCKS 3840
#define EBLOCKS 1024

__global__ void prep_all(const float* __restrict__ w, const float4* __restrict__ e) {
    __shared__ float t[64][33];
    const int b   = blockIdx.x;
    const int tid = threadIdx.x;

    if (b < WBLOCKS) {
        const int p   = b >> 5;           // 32 tiles per pair (4 e-tiles x 8 f-tiles)
        const int til = b & 31;
        const int e0  = (til >> 3) * 64;
        const int f0  = (til & 7) * 32;
        const float* W = w + (size_t)p * EMBED * EMBED;

        // load 64 x 32 tile: t[e][f], f-contiguous LDG (128B/warp)
        #pragma unroll
        for (int k = 0; k < 8; ++k) {
            const int idx = tid + k * 256;      // 0..2047
            const int el  = idx >> 5;           // 0..63
            const int fl  = idx & 31;           // 0..31
            t[el][fl] = W[(size_t)(e0 + el) * EMBED + f0 + fl];
        }
        __syncthreads();

        // store transposed as half2: 32 lanes -> 128 contiguous bytes
        __half* Wt = g_Wt + (size_t)p * EMBED * EMBED;
        #pragma unroll
        for (int k = 0; k < 4; ++k) {
            const int idx = tid + k * 256;      // 0..1023
            const int fl  = idx >> 5;           // 0..31
            const int ep  = idx & 31;           // 0..31 (e pair)
            __half2 v = __floats2half2_rn(t[2 * ep][fl], t[2 * ep + 1][fl]);
            *reinterpret_cast<__half2*>(Wt + (size_t)(f0 + fl) * EMBED + e0 + 2 * ep) = v;
        }
    } else {
        const size_t base = (size_t)(b - WBLOCKS) * 1024 + tid;   // pair-of-float4 index
        #pragma unroll
        for (int k = 0; k < 4; ++k) {
            const size_t pi = base + (size_t)k * 256;   // < 1,048,576
            float4 v0 = e[pi * 2];
            float4 v1 = e[pi * 2 + 1];
            uint4 o;
            o.x = h2_bits(__floats2half2_rn(v0.x, v0.y));
            o.y = h2_bits(__floats2half2_rn(v0.z, v0.w));
            o.z = h2_bits(__floats2half2_rn(v1.x, v1.y));
            o.w = h2_bits(__floats2half2_rn(v1.z, v1.w));
            reinterpret_cast<uint4*>(g_embh)[pi] = o;
        }
    }
}

// ---------------- main kernel (exact R11 structure) ----------------
__global__ void __launch_bounds__(THREADS, 2)
bilinear_kernel(const float* __restrict__ emb,
                const float* __restrict__ bias,
                float* __restrict__ out)
{
    extern __shared__ __half sm[];
    __half* Asm = sm;
    __half* Bsm = sm + 2 * TILE_HALFS;

    const int p   = blockIdx.z;
    const int bm0 = blockIdx.x * BM;
    const int bn0 = blockIdx.y * BN;

    // pair p -> (i, j) of triu_indices(16, k=1)
    int i = 0, rem = p;
    while (rem >= (NUM_FIELDS - 1) - i) { rem -= (NUM_FIELDS - 1) - i; ++i; }
    const int j = i + 1 + rem;

    const int tid  = threadIdx.x;
    const int lane = tid & 31;
    const int warp = tid >> 5;    // 0..3
    const int wm   = warp >> 1;   // 0..1  (64-row slab)
    const int wn   = warp & 1;    // 0..1  (64-col slab)
    const int g    = lane >> 2;   // 0..7
    const int t4   = lane & 3;    // 0..3

    const __half* Aglob = g_embh + (size_t)bm0 * (NUM_FIELDS * EMBED) + (size_t)i * EMBED;
    const __half* Bglob = g_Wt + (size_t)p * (EMBED * EMBED) + (size_t)bn0 * EMBED;

    float acc[4][8][4];
    #pragma unroll
    for (int mi = 0; mi < 4; ++mi)
        #pragma unroll
        for (int ni = 0; ni < 8; ++ni)
            #pragma unroll
            for (int r = 0; r < 4; ++r)
                acc[mi][ni][r] = 0.0f;

    // ---- async tile loaders: 128 rows x 64 halfs = 1024 x 16B per operand --
    auto load_tiles = [&](int buf, int k0) {
        __half* Ad = Asm + buf * TILE_HALFS;
        __half* Bd = Bsm + buf * TILE_HALFS;
        #pragma unroll
        for (int it = 0; it < 8; ++it) {
            int idx = tid + it * THREADS;
            int m   = idx >> 3;          // 0..127
            int q   = idx & 7;           // 8-half chunk
            cp_async16(smem_u32(Ad + m * STRIDE + q * 8),
                       Aglob + (size_t)m * (NUM_FIELDS * EMBED) + k0 + q * 8);
        }
        #pragma unroll
        for (int it = 0; it < 8; ++it) {
            int idx = tid + it * THREADS;
            int n   = idx >> 3;
            int q   = idx & 7;
            cp_async16(smem_u32(Bd + n * STRIDE + q * 8),
                       Bglob + (size_t)n * EMBED + k0 + q * 8);
        }
    };

    const int NK = EMBED / BK;   // 4

    load_tiles(0, 0);
    cp_commit();

    for (int kt = 0; kt < NK; ++kt) {
        if (kt + 1 < NK) {
            load_tiles((kt + 1) & 1, (kt + 1) * BK);
            cp_commit();
            asm volatile("cp.async.wait_group 1;\n" ::: "memory");
        } else {
            asm volatile("cp.async.wait_group 0;\n" ::: "memory");
        }
        __syncthreads();

        const __half* Ab = Asm + (kt & 1) * TILE_HALFS;
        const __half* Bb = Bsm + (kt & 1) * TILE_HALFS;

        #pragma unroll
        for (int ks = 0; ks < BK / 16; ++ks) {
            const int kk = ks * 16;

            uint32_t afrag[4][4];
            #pragma unroll
            for (int mi = 0; mi < 4; ++mi) {
                const int rm = wm * 64 + mi * 16;
                afrag[mi][0] = *(const uint32_t*)(Ab + (rm + g    ) * STRIDE + kk + 2 * t4    );
                afrag[mi][1] = *(const uint32_t*)(Ab + (rm + g + 8) * STRIDE + kk + 2 * t4    );
                afrag[mi][2] = *(const uint32_t*)(Ab + (rm + g    ) * STRIDE + kk + 2 * t4 + 8);
                afrag[mi][3] = *(const uint32_t*)(Ab + (rm + g + 8) * STRIDE + kk + 2 * t4 + 8);
            }
            uint32_t bfrag[8][2];
            #pragma unroll
            for (int ni = 0; ni < 8; ++ni) {
                const int cn = wn * 64 + ni * 8 + g;
                bfrag[ni][0] = *(const uint32_t*)(Bb + cn * STRIDE + kk + 2 * t4    );
                bfrag[ni][1] = *(const uint32_t*)(Bb + cn * STRIDE + kk + 2 * t4 + 8);
            }
            #pragma unroll
            for (int mi = 0; mi < 4; ++mi)
                #pragma unroll
                for (int ni = 0; ni < 8; ++ni)
                    mma_f16(acc[mi][ni], afrag[mi], bfrag[ni]);
        }
        __syncthreads();
    }

    // ---- epilogue: out[b,p,f] = acc * emb[b,j,f] + bias[p,f] ---------------
    const float* biasP = bias + (size_t)p * EMBED;

    #pragma unroll
    for (int mi = 0; mi < 4; ++mi) {
        const int r0 = bm0 + wm * 64 + mi * 16 + g;
        #pragma unroll
        for (int ni = 0; ni < 8; ++ni) {
            const int c = bn0 + wn * 64 + ni * 8 + t4 * 2;
            const float2 bb = *(const float2*)(biasP + c);
            #pragma unroll
            for (int h = 0; h < 2; ++h) {
                const int row = r0 + h * 8;
                const float2 q = *(const float2*)(emb + (size_t)row * (NUM_FIELDS * EMBED)
                                                   + (size_t)j * EMBED + c);
                float2 v;
                v.x = acc[mi][ni][h * 2 + 0] * q.x + bb.x;
                v.y = acc[mi][ni][h * 2 + 1] * q.y + bb.y;
                *(float2*)(out + (size_t)row * (NUM_PAIRS * EMBED) + (size_t)p * EMBED + c) = v;
            }
        }
    }
}

extern "C" void kernel_launch(void* const* d_in, const int* in_sizes, int n_in,
                              void* d_out, int out_size) {
    const float* emb    = (const float*)d_in[0];
    const float* weight = (const float*)d_in[1];
    const float* bias   = (const float*)d_in[2];
    float* out          = (float*)d_out;

    cudaFuncSetAttribute(bilinear_kernel,
                         cudaFuncAttributeMaxDynamicSharedMemorySize, SMEM_BYTES);

    prep_all<<<WBLOCKS + EBLOCKS, 256>>>(weight, (const float4*)emb);

    dim3 grid(BATCH / BM, EMBED / BN, NUM_PAIRS);   // (16, 2, 120)
    bilinear_kernel<<<grid, THREADS, SMEM_BYTES>>>(emb, bias, out);
}

// round 17
// speedup vs baseline: 1.1766x; 1.0653x over previous
#include <cuda_runtime.h>
#include <cuda_fp16.h>
#include <cstdint>

// Problem constants
#define NUM_FIELDS 16
#define EMBED      256
#define BATCH      2048
#define NUM_PAIRS  120

// Tiling: CTA 128x128 with 4 warps (2x2), warp tile 64x64, BK=64, fp16 m16n8k16
#define BM 128
#define BN 128
#define BK 64
#define THREADS 128

#define STRIDE 72                 // halfs; fragment banks conflict-free (proven R9-R16)
#define TILE_HALFS (128 * STRIDE) // per operand per stage
#define SMEM_BYTES (4 * TILE_HALFS * 2)   // 73728 B (>= 128*132*4 = 67584 for epilogue)

#define EPI_STRIDE 132            // fp32 words per row in epilogue tile (528B, 16B-aligned)

// fp16 copies (allocation-free rule: __device__ globals)
__device__ __half g_Wt[(size_t)NUM_PAIRS * EMBED * EMBED];   // W^T: [p][f][e]
__device__ __half g_embh[(size_t)BATCH * NUM_FIELDS * EMBED];

__device__ __forceinline__ uint32_t smem_u32(const void* p) {
    return (uint32_t)__cvta_generic_to_shared(p);
}
__device__ __forceinline__ void cp_async16(uint32_t dst, const void* src) {
    asm volatile("cp.async.cg.shared.global [%0], [%1], 16;\n" :: "r"(dst), "l"(src));
}
__device__ __forceinline__ void cp_commit() {
    asm volatile("cp.async.commit_group;\n" ::: "memory");
}
__device__ __forceinline__ uint32_t h2_bits(__half2 h) {
    return *reinterpret_cast<uint32_t*>(&h);
}
__device__ __forceinline__ void mma_f16(float c[4], const uint32_t a[4], const uint32_t b[2]) {
    asm volatile(
        "mma.sync.aligned.m16n8k16.row.col.f32.f16.f16.f32 "
        "{%0,%1,%2,%3}, {%4,%5,%6,%7}, {%8,%9}, {%0,%1,%2,%3};\n"
        : "+f"(c[0]), "+f"(c[1]), "+f"(c[2]), "+f"(c[3])
        : "r"(a[0]), "r"(a[1]), "r"(a[2]), "r"(a[3]), "r"(b[0]), "r"(b[1]));
}

// ---------------- fused prep kernel (vectorized stores) ----------------
#define WBLOCKS 3840
#define EBLOCKS 1024

__global__ void prep_all(const float* __restrict__ w, const float4* __restrict__ e) {
    __shared__ float t[64][33];
    const int b   = blockIdx.x;
    const int tid = threadIdx.x;

    if (b < WBLOCKS) {
        const int p   = b >> 5;           // 32 tiles per pair (4 e-tiles x 8 f-tiles)
        const int til = b & 31;
        const int e0  = (til >> 3) * 64;
        const int f0  = (til & 7) * 32;
        const float* W = w + (size_t)p * EMBED * EMBED;

        #pragma unroll
        for (int k = 0; k < 8; ++k) {
            const int idx = tid + k * 256;
            const int el  = idx >> 5;
            const int fl  = idx & 31;
            t[el][fl] = W[(size_t)(e0 + el) * EMBED + f0 + fl];
        }
        __syncthreads();

        __half* Wt = g_Wt + (size_t)p * EMBED * EMBED;
        #pragma unroll
        for (int k = 0; k < 4; ++k) {
            const int idx = tid + k * 256;
            const int fl  = idx >> 5;
            const int ep  = idx & 31;
            __half2 v = __floats2half2_rn(t[2 * ep][fl], t[2 * ep + 1][fl]);
            *reinterpret_cast<__half2*>(Wt + (size_t)(f0 + fl) * EMBED + e0 + 2 * ep) = v;
        }
    } else {
        const size_t base = (size_t)(b - WBLOCKS) * 1024 + tid;
        #pragma unroll
        for (int k = 0; k < 4; ++k) {
            const size_t pi = base + (size_t)k * 256;
            float4 v0 = e[pi * 2];
            float4 v1 = e[pi * 2 + 1];
            uint4 o;
            o.x = h2_bits(__floats2half2_rn(v0.x, v0.y));
            o.y = h2_bits(__floats2half2_rn(v0.z, v0.w));
            o.z = h2_bits(__floats2half2_rn(v1.x, v1.y));
            o.w = h2_bits(__floats2half2_rn(v1.z, v1.w));
            reinterpret_cast<uint4*>(g_embh)[pi] = o;
        }
    }
}

// ---------------- main kernel (R11 mainloop + smem-staged epilogue) --------
__global__ void __launch_bounds__(THREADS, 2)
bilinear_kernel(const float* __restrict__ emb,
                const float* __restrict__ bias,
                float* __restrict__ out)
{
    extern __shared__ __half sm[];
    __half* Asm = sm;
    __half* Bsm = sm + 2 * TILE_HALFS;

    const int p   = blockIdx.z;
    const int bm0 = blockIdx.x * BM;
    const int bn0 = blockIdx.y * BN;

    // pair p -> (i, j) of triu_indices(16, k=1)
    int i = 0, rem = p;
    while (rem >= (NUM_FIELDS - 1) - i) { rem -= (NUM_FIELDS - 1) - i; ++i; }
    const int j = i + 1 + rem;

    const int tid  = threadIdx.x;
    const int lane = tid & 31;
    const int warp = tid >> 5;    // 0..3
    const int wm   = warp >> 1;   // 0..1  (64-row slab)
    const int wn   = warp & 1;    // 0..1  (64-col slab)
    const int g    = lane >> 2;   // 0..7
    const int t4   = lane & 3;    // 0..3

    const __half* Aglob = g_embh + (size_t)bm0 * (NUM_FIELDS * EMBED) + (size_t)i * EMBED;
    const __half* Bglob = g_Wt + (size_t)p * (EMBED * EMBED) + (size_t)bn0 * EMBED;

    float acc[4][8][4];
    #pragma unroll
    for (int mi = 0; mi < 4; ++mi)
        #pragma unroll
        for (int ni = 0; ni < 8; ++ni)
            #pragma unroll
            for (int r = 0; r < 4; ++r)
                acc[mi][ni][r] = 0.0f;

    // ---- async tile loaders: 128 rows x 64 halfs = 1024 x 16B per operand --
    auto load_tiles = [&](int buf, int k0) {
        __half* Ad = Asm + buf * TILE_HALFS;
        __half* Bd = Bsm + buf * TILE_HALFS;
        #pragma unroll
        for (int it = 0; it < 8; ++it) {
            int idx = tid + it * THREADS;
            int m   = idx >> 3;          // 0..127
            int q   = idx & 7;           // 8-half chunk
            cp_async16(smem_u32(Ad + m * STRIDE + q * 8),
                       Aglob + (size_t)m * (NUM_FIELDS * EMBED) + k0 + q * 8);
        }
        #pragma unroll
        for (int it = 0; it < 8; ++it) {
            int idx = tid + it * THREADS;
            int n   = idx >> 3;
            int q   = idx & 7;
            cp_async16(smem_u32(Bd + n * STRIDE + q * 8),
                       Bglob + (size_t)n * EMBED + k0 + q * 8);
        }
    };

    const int NK = EMBED / BK;   // 4

    load_tiles(0, 0);
    cp_commit();

    for (int kt = 0; kt < NK; ++kt) {
        if (kt + 1 < NK) {
            load_tiles((kt + 1) & 1, (kt + 1) * BK);
            cp_commit();
            asm volatile("cp.async.wait_group 1;\n" ::: "memory");
        } else {
            asm volatile("cp.async.wait_group 0;\n" ::: "memory");
        }
        __syncthreads();

        const __half* Ab = Asm + (kt & 1) * TILE_HALFS;
        const __half* Bb = Bsm + (kt & 1) * TILE_HALFS;

        #pragma unroll
        for (int ks = 0; ks < BK / 16; ++ks) {
            const int kk = ks * 16;

            uint32_t afrag[4][4];
            #pragma unroll
            for (int mi = 0; mi < 4; ++mi) {
                const int rm = wm * 64 + mi * 16;
                afrag[mi][0] = *(const uint32_t*)(Ab + (rm + g    ) * STRIDE + kk + 2 * t4    );
                afrag[mi][1] = *(const uint32_t*)(Ab + (rm + g + 8) * STRIDE + kk + 2 * t4    );
                afrag[mi][2] = *(const uint32_t*)(Ab + (rm + g    ) * STRIDE + kk + 2 * t4 + 8);
                afrag[mi][3] = *(const uint32_t*)(Ab + (rm + g + 8) * STRIDE + kk + 2 * t4 + 8);
            }
            uint32_t bfrag[8][2];
            #pragma unroll
            for (int ni = 0; ni < 8; ++ni) {
                const int cn = wn * 64 + ni * 8 + g;
                bfrag[ni][0] = *(const uint32_t*)(Bb + cn * STRIDE + kk + 2 * t4    );
                bfrag[ni][1] = *(const uint32_t*)(Bb + cn * STRIDE + kk + 2 * t4 + 8);
            }
            #pragma unroll
            for (int mi = 0; mi < 4; ++mi)
                #pragma unroll
                for (int ni = 0; ni < 8; ++ni)
                    mma_f16(acc[mi][ni], afrag[mi], bfrag[ni]);
        }
        __syncthreads();
    }

    // ---- epilogue: smem-staged transpose for coalesced q/out traffic -------
    float* tile = reinterpret_cast<float*>(sm);   // 128 x EPI_STRIDE fp32

    // Phase 1: scatter acc into smem tile (local layout [row][col])
    #pragma unroll
    for (int mi = 0; mi < 4; ++mi) {
        const int r0 = wm * 64 + mi * 16 + g;
        #pragma unroll
        for (int ni = 0; ni < 8; ++ni) {
            const int c = wn * 64 + ni * 8 + t4 * 2;
            #pragma unroll
            for (int h = 0; h < 2; ++h) {
                const int row = r0 + h * 8;
                *reinterpret_cast<float2*>(tile + row * EPI_STRIDE + c) =
                    make_float2(acc[mi][ni][h * 2 + 0], acc[mi][ni][h * 2 + 1]);
            }
        }
    }
    __syncthreads();

    // Phase 2: warp w sweeps rows w, w+4, ...; lanes cover one float4 each
    const float* biasP = bias + (size_t)p * EMBED + bn0;
    const float4 bb = *(const float4*)(biasP + lane * 4);

    for (int r = warp; r < BM; r += 4) {
        const int grow = bm0 + r;
        const float4 s = *(const float4*)(tile + r * EPI_STRIDE + lane * 4);
        const float4 q = *(const float4*)(emb + (size_t)grow * (NUM_FIELDS * EMBED)
                                           + (size_t)j * EMBED + bn0 + lane * 4);
        float4 v;
        v.x = s.x * q.x + bb.x;
        v.y = s.y * q.y + bb.y;
        v.z = s.z * q.z + bb.z;
        v.w = s.w * q.w + bb.w;
        *reinterpret_cast<float4*>(out + (size_t)grow * (NUM_PAIRS * EMBED)
                                   + (size_t)p * EMBED + bn0 + lane * 4) = v;
    }
}

extern "C" void kernel_launch(void* const* d_in, const int* in_sizes, int n_in,
                              void* d_out, int out_size) {
    const float* emb    = (const float*)d_in[0];
    const float* weight = (const float*)d_in[1];
    const float* bias   = (const float*)d_in[2];
    float* out          = (float*)d_out;

    cudaFuncSetAttribute(bilinear_kernel,
                         cudaFuncAttributeMaxDynamicSharedMemorySize, SMEM_BYTES);

    prep_all<<<WBLOCKS + EBLOCKS, 256>>>(weight, (const float4*)emb);

    dim3 grid(BATCH / BM, EMBED / BN, NUM_PAIRS);   // (16, 2, 120)
    bilinear_kernel<<<grid, THREADS, SMEM_BYTES>>>(emb, bias, out);
}